// round 1
// baseline (speedup 1.0000x reference)
#include <cuda_runtime.h>
#include <cstddef>

#define BATCH 256
#define SEQ   512
#define DIN   64
#define HID   512
#define GRIDN 128
#define NTH   256

#define TM 64
#define TN 64
#define KA_PER 144          // 576 / 4
#define KB_PER 256          // 1024 / 4
#define CHUNK 16
#define NC_A (KA_PER / CHUNK)   // 9
#define NC_B (KB_PER / CHUNK)   // 16

#define SMEM_BYTES 122880   // > 113.5KB -> forces 1 CTA/SM; actual use ~110.6KB

// Mutable cross-CTA state (scratch; allocation-free per harness rules)
__device__ float g_H1[BATCH * HID];
__device__ float g_H2[BATCH * HID];
__device__ float g_P[4 * BATCH * HID];
__device__ unsigned g_bar_cnt;
__device__ volatile unsigned g_bar_gen;

__device__ __forceinline__ void grid_sync() {
    __syncthreads();
    if (threadIdx.x == 0) {
        unsigned gen = g_bar_gen;
        __threadfence();
        if (atomicAdd(&g_bar_cnt, 1u) == GRIDN - 1u) {
            g_bar_cnt = 0u;
            __threadfence();
            g_bar_gen = gen + 1u;
        } else {
            while (g_bar_gen == gen) { __nanosleep(32); }
        }
        __threadfence();
    }
    __syncthreads();
}

__global__ void __launch_bounds__(NTH, 1) rnn_persistent(
    const float* __restrict__ x,
    const float* __restrict__ W_ih0, const float* __restrict__ W_hh0,
    const float* __restrict__ b_ih0, const float* __restrict__ b_hh0,
    const float* __restrict__ W_ih1, const float* __restrict__ W_hh1,
    const float* __restrict__ b_ih1, const float* __restrict__ b_hh1,
    const float* __restrict__ W_fc,  const float* __restrict__ b_fc,
    float* __restrict__ out)
{
    const int tid  = threadIdx.x;
    const int bid  = blockIdx.x;
    const int ks   = bid & 3;        // K-split index 0..3
    const int tile = bid >> 2;       // 0..31
    const int mt   = tile >> 3;      // 0..3
    const int nt   = tile & 7;       // 0..7
    const int m0   = mt * TM;
    const int n0   = nt * TN;

    extern __shared__ float smem[];
    float* Ws_a = smem;                      // [KA_PER][TN]  36,864 B
    float* Ws_b = Ws_a + KA_PER * TN;        // [KB_PER][TN]  65,536 B
    float* As   = Ws_b + KB_PER * TN;        // [2][CHUNK][TM] 8,192 B

    // ---------- one-time: weight slices -> SMEM (resident whole kernel) ----------
    {
        const int kb = ks * KA_PER;
        for (int idx = tid; idx < KA_PER * TN; idx += NTH) {
            int n  = idx / KA_PER;
            int k  = idx - n * KA_PER;
            int kg = kb + k;
            Ws_a[k * TN + n] = (kg < DIN) ? W_ih0[(n0 + n) * DIN + kg]
                                          : W_hh0[(n0 + n) * HID + (kg - DIN)];
        }
        const int kbb = ks * KB_PER;
        for (int idx = tid; idx < KB_PER * TN; idx += NTH) {
            int n  = idx / KB_PER;
            int k  = idx - n * KB_PER;
            int kg = kbb + k;
            Ws_b[k * TN + n] = (kg < HID) ? W_ih1[(n0 + n) * HID + kg]
                                          : W_hh1[(n0 + n) * HID + (kg - HID)];
        }
    }
    // ---------- zero hidden states ----------
    {
        const int per  = (BATCH * HID) / GRIDN;  // 1024
        const int base = bid * per;
        for (int i = tid; i < per; i += NTH) {
            g_H1[base + i] = 0.f;
            g_H2[base + i] = 0.f;
        }
    }
    grid_sync();

    const int tm   = tid & 15;   // m-quad
    const int tn   = tid >> 4;   // n-quad
    const int mm   = tid & 63;   // staging: row
    const int kq   = tid >> 6;   // staging: k-quad (0..3)
    const int m_ld = m0 + mm;

    for (int t = 0; t < SEQ; ++t) {
        // ============================ phase A: compute ============================
        {
            float acc[4][4];
            #pragma unroll
            for (int i = 0; i < 4; i++)
                #pragma unroll
                for (int j = 0; j < 4; j++) acc[i][j] = 0.f;

            const int kb = ks * KA_PER;
            auto ldA = [&](int c) -> float4 {
                int kg = kb + c * CHUNK + kq * 4;
                if (kg < DIN)
                    return *(const float4*)(x + ((size_t)m_ld * SEQ + t) * DIN + kg);
                return __ldcg((const float4*)(g_H1 + (size_t)m_ld * HID + (kg - DIN)));
            };
            float4 v = ldA(0);
            for (int c = 0; c < NC_A; ++c) {
                float* dst = As + (c & 1) * (CHUNK * TM);
                dst[(kq * 4 + 0) * TM + mm] = v.x;
                dst[(kq * 4 + 1) * TM + mm] = v.y;
                dst[(kq * 4 + 2) * TM + mm] = v.z;
                dst[(kq * 4 + 3) * TM + mm] = v.w;
                __syncthreads();
                v = ldA((c + 1 < NC_A) ? c + 1 : 0);   // prefetch (dummy wrap on last)
                const float* Ab = As + (c & 1) * (CHUNK * TM);
                const float* Wb = Ws_a + c * CHUNK * TN;
                #pragma unroll
                for (int kk = 0; kk < CHUNK; ++kk) {
                    float4 av = *(const float4*)(Ab + kk * TM + tm * 4);
                    float4 wv = *(const float4*)(Wb + kk * TN + tn * 4);
                    acc[0][0] = fmaf(av.x, wv.x, acc[0][0]);
                    acc[0][1] = fmaf(av.x, wv.y, acc[0][1]);
                    acc[0][2] = fmaf(av.x, wv.z, acc[0][2]);
                    acc[0][3] = fmaf(av.x, wv.w, acc[0][3]);
                    acc[1][0] = fmaf(av.y, wv.x, acc[1][0]);
                    acc[1][1] = fmaf(av.y, wv.y, acc[1][1]);
                    acc[1][2] = fmaf(av.y, wv.z, acc[1][2]);
                    acc[1][3] = fmaf(av.y, wv.w, acc[1][3]);
                    acc[2][0] = fmaf(av.z, wv.x, acc[2][0]);
                    acc[2][1] = fmaf(av.z, wv.y, acc[2][1]);
                    acc[2][2] = fmaf(av.z, wv.z, acc[2][2]);
                    acc[2][3] = fmaf(av.z, wv.w, acc[2][3]);
                    acc[3][0] = fmaf(av.w, wv.x, acc[3][0]);
                    acc[3][1] = fmaf(av.w, wv.y, acc[3][1]);
                    acc[3][2] = fmaf(av.w, wv.z, acc[3][2]);
                    acc[3][3] = fmaf(av.w, wv.w, acc[3][3]);
                }
            }
            float* P = g_P + (size_t)ks * BATCH * HID;
            #pragma unroll
            for (int i = 0; i < 4; i++) {
                int m = m0 + tm * 4 + i;
                float4 r = make_float4(acc[i][0], acc[i][1], acc[i][2], acc[i][3]);
                *(float4*)(P + (size_t)m * HID + n0 + tn * 4) = r;
            }
        }
        grid_sync();
        // ============================ reduce A -> H1 ============================
        {
            int o = (bid << 10) + (tid << 2);
            int b = o >> 9;
            int n = o & (HID - 1);
            const float* Pb = g_P + (size_t)b * HID + n;
            float4 p0 = __ldcg((const float4*)(Pb + (size_t)0 * BATCH * HID));
            float4 p1 = __ldcg((const float4*)(Pb + (size_t)1 * BATCH * HID));
            float4 p2 = __ldcg((const float4*)(Pb + (size_t)2 * BATCH * HID));
            float4 p3 = __ldcg((const float4*)(Pb + (size_t)3 * BATCH * HID));
            float4 bi = *(const float4*)(b_ih0 + n);
            float4 bh = *(const float4*)(b_hh0 + n);
            float4 h;
            h.x = tanhf(bi.x + bh.x + p0.x + p1.x + p2.x + p3.x);
            h.y = tanhf(bi.y + bh.y + p0.y + p1.y + p2.y + p3.y);
            h.z = tanhf(bi.z + bh.z + p0.z + p1.z + p2.z + p3.z);
            h.w = tanhf(bi.w + bh.w + p0.w + p1.w + p2.w + p3.w);
            *(float4*)(g_H1 + (size_t)b * HID + n) = h;
        }
        grid_sync();
        // ============================ phase B: compute ============================
        {
            float acc[4][4];
            #pragma unroll
            for (int i = 0; i < 4; i++)
                #pragma unroll
                for (int j = 0; j < 4; j++) acc[i][j] = 0.f;

            const int kb = ks * KB_PER;
            auto ldB = [&](int c) -> float4 {
                int kg = kb + c * CHUNK + kq * 4;
                const float* src = (kg < HID)
                    ? (g_H1 + (size_t)m_ld * HID + kg)
                    : (g_H2 + (size_t)m_ld * HID + (kg - HID));
                return __ldcg((const float4*)src);
            };
            float4 v = ldB(0);
            for (int c = 0; c < NC_B; ++c) {
                float* dst = As + (c & 1) * (CHUNK * TM);
                dst[(kq * 4 + 0) * TM + mm] = v.x;
                dst[(kq * 4 + 1) * TM + mm] = v.y;
                dst[(kq * 4 + 2) * TM + mm] = v.z;
                dst[(kq * 4 + 3) * TM + mm] = v.w;
                __syncthreads();
                v = ldB((c + 1 < NC_B) ? c + 1 : 0);
                const float* Ab = As + (c & 1) * (CHUNK * TM);
                const float* Wb = Ws_b + c * CHUNK * TN;
                #pragma unroll
                for (int kk = 0; kk < CHUNK; ++kk) {
                    float4 av = *(const float4*)(Ab + kk * TM + tm * 4);
                    float4 wv = *(const float4*)(Wb + kk * TN + tn * 4);
                    acc[0][0] = fmaf(av.x, wv.x, acc[0][0]);
                    acc[0][1] = fmaf(av.x, wv.y, acc[0][1]);
                    acc[0][2] = fmaf(av.x, wv.z, acc[0][2]);
                    acc[0][3] = fmaf(av.x, wv.w, acc[0][3]);
                    acc[1][0] = fmaf(av.y, wv.x, acc[1][0]);
                    acc[1][1] = fmaf(av.y, wv.y, acc[1][1]);
                    acc[1][2] = fmaf(av.y, wv.z, acc[1][2]);
                    acc[1][3] = fmaf(av.y, wv.w, acc[1][3]);
                    acc[2][0] = fmaf(av.z, wv.x, acc[2][0]);
                    acc[2][1] = fmaf(av.z, wv.y, acc[2][1]);
                    acc[2][2] = fmaf(av.z, wv.z, acc[2][2]);
                    acc[2][3] = fmaf(av.z, wv.w, acc[2][3]);
                    acc[3][0] = fmaf(av.w, wv.x, acc[3][0]);
                    acc[3][1] = fmaf(av.w, wv.y, acc[3][1]);
                    acc[3][2] = fmaf(av.w, wv.z, acc[3][2]);
                    acc[3][3] = fmaf(av.w, wv.w, acc[3][3]);
                }
            }
            float* P = g_P + (size_t)ks * BATCH * HID;
            #pragma unroll
            for (int i = 0; i < 4; i++) {
                int m = m0 + tm * 4 + i;
                float4 r = make_float4(acc[i][0], acc[i][1], acc[i][2], acc[i][3]);
                *(float4*)(P + (size_t)m * HID + n0 + tn * 4) = r;
            }
        }
        grid_sync();
        // ============================ reduce B -> H2 ============================
        {
            int o = (bid << 10) + (tid << 2);
            int b = o >> 9;
            int n = o & (HID - 1);
            const float* Pb = g_P + (size_t)b * HID + n;
            float4 p0 = __ldcg((const float4*)(Pb + (size_t)0 * BATCH * HID));
            float4 p1 = __ldcg((const float4*)(Pb + (size_t)1 * BATCH * HID));
            float4 p2 = __ldcg((const float4*)(Pb + (size_t)2 * BATCH * HID));
            float4 p3 = __ldcg((const float4*)(Pb + (size_t)3 * BATCH * HID));
            float4 bi = *(const float4*)(b_ih1 + n);
            float4 bh = *(const float4*)(b_hh1 + n);
            float4 h;
            h.x = tanhf(bi.x + bh.x + p0.x + p1.x + p2.x + p3.x);
            h.y = tanhf(bi.y + bh.y + p0.y + p1.y + p2.y + p3.y);
            h.z = tanhf(bi.z + bh.z + p0.z + p1.z + p2.z + p3.z);
            h.w = tanhf(bi.w + bh.w + p0.w + p1.w + p2.w + p3.w);
            *(float4*)(g_H2 + (size_t)b * HID + n) = h;
        }
        grid_sync();
    }

    // ============================ final FC: out[b] = H2[b,:] . W_fc + b_fc ============================
    __shared__ float red[8];
    for (int r = 0; r < 2; ++r) {
        int b = bid * 2 + r;
        float s = 0.f;
        for (int h = tid; h < HID; h += NTH)
            s += __ldcg(g_H2 + (size_t)b * HID + h) * W_fc[h];
        #pragma unroll
        for (int off = 16; off; off >>= 1)
            s += __shfl_down_sync(0xffffffffu, s, off);
        if ((tid & 31) == 0) red[tid >> 5] = s;
        __syncthreads();
        if (tid == 0) {
            float tot = b_fc[0];
            #pragma unroll
            for (int w = 0; w < 8; w++) tot += red[w];
            out[b] = tot;
        }
        __syncthreads();
    }
}

extern "C" void kernel_launch(void* const* d_in, const int* in_sizes, int n_in,
                              void* d_out, int out_size) {
    (void)in_sizes; (void)n_in; (void)out_size;
    const float* x     = (const float*)d_in[0];
    const float* W_ih0 = (const float*)d_in[1];
    const float* W_hh0 = (const float*)d_in[2];
    const float* b_ih0 = (const float*)d_in[3];
    const float* b_hh0 = (const float*)d_in[4];
    const float* W_ih1 = (const float*)d_in[5];
    const float* W_hh1 = (const float*)d_in[6];
    const float* b_ih1 = (const float*)d_in[7];
    const float* b_hh1 = (const float*)d_in[8];
    const float* W_fc  = (const float*)d_in[9];
    const float* b_fc  = (const float*)d_in[10];
    float* out = (float*)d_out;

    cudaFuncSetAttribute(rnn_persistent,
                         cudaFuncAttributeMaxDynamicSharedMemorySize, SMEM_BYTES);
    rnn_persistent<<<GRIDN, NTH, SMEM_BYTES>>>(
        x, W_ih0, W_hh0, b_ih0, b_hh0,
        W_ih1, W_hh1, b_ih1, b_hh1, W_fc, b_fc, out);
}